// round 5
// baseline (speedup 1.0000x reference)
#include <cuda_runtime.h>
#include <cuda_bf16.h>
#include <math.h>
#include <stdint.h>

#define BATCH   8
#define SEQ     1024
#define HID     768
#define NHEADS  12
#define HDIM    64
#define QKV_N   (3*HID)          // 2304
#define MTOT    (BATCH*SEQ)      // 8192

__device__ float g_x[(size_t)MTOT * HID];        // tf32-rounded x
__device__ float g_qkv[(size_t)MTOT * QKV_N];    // [B*S, 2304]
__device__ float g_o[(size_t)MTOT * HID];        // [B*S, 768] (tf32-rounded)
__device__ float g_wt_qkv[(size_t)QKV_N * HID];  // Wqkv^T (tf32-rounded)
__device__ float g_wt_out[(size_t)HID * HID];    // Wout^T (tf32-rounded)

// ---------------------------------------------------------------------------
// helpers
// ---------------------------------------------------------------------------
__device__ __forceinline__ uint32_t smem_u32(const void* p) {
    uint32_t a;
    asm("{ .reg .u64 t; cvta.to.shared.u64 t, %1; cvt.u32.u64 %0, t; }" : "=r"(a) : "l"(p));
    return a;
}
__device__ __forceinline__ uint32_t f2tf32(float f) {
    uint32_t r;
    asm("cvt.rna.tf32.f32 %0, %1;" : "=r"(r) : "f"(f));
    return r;
}
__device__ __forceinline__ uint4 cvt4(float4 v) {
    uint4 r;
    r.x = f2tf32(v.x); r.y = f2tf32(v.y); r.z = f2tf32(v.z); r.w = f2tf32(v.w);
    return r;
}
__device__ __forceinline__ void mma_tf32(float* c,
                                         uint32_t a0, uint32_t a1, uint32_t a2, uint32_t a3,
                                         uint32_t b0, uint32_t b1) {
    asm volatile(
        "mma.sync.aligned.m16n8k8.row.col.f32.tf32.tf32.f32 "
        "{%0,%1,%2,%3}, {%4,%5,%6,%7}, {%8,%9}, {%0,%1,%2,%3};"
        : "+f"(c[0]), "+f"(c[1]), "+f"(c[2]), "+f"(c[3])
        : "r"(a0), "r"(a1), "r"(a2), "r"(a3), "r"(b0), "r"(b1));
}
#define LDSM_X4(r0, r1, r2, r3, addr) \
    asm volatile("ldmatrix.sync.aligned.m8n8.x4.shared.b16 {%0,%1,%2,%3}, [%4];" \
        : "=r"(r0), "=r"(r1), "=r"(r2), "=r"(r3) : "r"(addr))
__device__ __forceinline__ void cp16(uint32_t dst, const void* src) {
    asm volatile("cp.async.cg.shared.global [%0], [%1], 16;" :: "r"(dst), "l"(src));
}
#define CP_COMMIT() asm volatile("cp.async.commit_group;" ::: "memory")
#define CP_WAIT1()  asm volatile("cp.async.wait_group 1;" ::: "memory")
#define CP_WAIT0()  asm volatile("cp.async.wait_group 0;" ::: "memory")

// ---------------------------------------------------------------------------
// tf32 GEMM (mma.sync + cp.async + ldmatrix), unchanged from round 4.
// Operands are pre-rounded to tf32 in memory, so truncation here is lossless.
// ---------------------------------------------------------------------------
#define KT       32
#define NCH      (768/KT)
#define STG_FLT  8192
#define GEMM_SMEM (3 * STG_FLT * 4)   // 98304

__global__ __launch_bounds__(256, 2)
void gemm_mma(const float* __restrict__ A, const float* __restrict__ Bt,
              float* __restrict__ C, int N,
              const float* __restrict__ bias,
              const float* __restrict__ scale,
              const float* __restrict__ shift)
{
    extern __shared__ float smem[];
    const uint32_t sb = smem_u32(smem);
    const int tid  = threadIdx.x;
    const int lane = tid & 31;
    const int warp = tid >> 5;
    const int g = lane >> 2;
    const int q = lane & 3;
    const int wm0 = (warp >> 2) * 64;
    const int wn0 = (warp & 3) * 32;
    const int m0 = blockIdx.y * 128;
    const int n0 = blockIdx.x * 128;

    float acc[4][4][4];
#pragma unroll
    for (int mf = 0; mf < 4; mf++)
#pragma unroll
        for (int nf = 0; nf < 4; nf++)
#pragma unroll
            for (int cc = 0; cc < 4; cc++) acc[mf][nf][cc] = 0.f;

    const int r_ld = tid >> 3;
    const int u_ld = tid & 7;
    const int rowA_l = lane & 15;
    const int rowB_l = lane & 7;
    const int selA = lane >> 4;
    const int selB = lane >> 3;

#define LOAD_STAGE(s, kc) do { \
    uint32_t ab = sb + (s) * (STG_FLT * 4); \
    uint32_t bb = ab + 16384; \
    _Pragma("unroll") \
    for (int i = 0; i < 4; i++) { \
        int r = r_ld + i * 32; \
        uint32_t off = ((uint32_t)(r * 8 + (u_ld ^ (r & 7)))) << 4; \
        cp16(ab + off, A  + (size_t)(m0 + r) * 768 + (kc) * KT + u_ld * 4); \
        cp16(bb + off, Bt + (size_t)(n0 + r) * 768 + (kc) * KT + u_ld * 4); \
    } \
} while (0)

    LOAD_STAGE(0, 0); CP_COMMIT();
    LOAD_STAGE(1, 1); CP_COMMIT();

    for (int kc = 0; kc < NCH; kc++) {
        if (kc >= NCH - 2) { CP_WAIT0(); } else { CP_WAIT1(); }
        __syncthreads();
        if (kc + 2 < NCH) {
            LOAD_STAGE((kc + 2) % 3, kc + 2);
            CP_COMMIT();
        }
        const uint32_t ab = sb + (kc % 3) * (STG_FLT * 4);
        const uint32_t bb = ab + 16384;

#pragma unroll
        for (int ksp = 0; ksp < 2; ksp++) {
            uint32_t bf[4][4];
#pragma unroll
            for (int nf = 0; nf < 4; nf++) {
                int row = wn0 + nf * 8 + rowB_l;
                uint32_t addr = bb + row * 128 +
                                (((4 * ksp + selB) ^ (row & 7)) << 4);
                LDSM_X4(bf[nf][0], bf[nf][1], bf[nf][2], bf[nf][3], addr);
            }
#pragma unroll
            for (int k2 = 0; k2 < 2; k2++) {
                int ks = ksp * 2 + k2;
                uint32_t af[4][4];
#pragma unroll
                for (int mf = 0; mf < 4; mf++) {
                    int row = wm0 + mf * 16 + rowA_l;
                    uint32_t addr = ab + row * 128 +
                                    (((2 * ks + selA) ^ (row & 7)) << 4);
                    LDSM_X4(af[mf][0], af[mf][1], af[mf][2], af[mf][3], addr);
                }
#pragma unroll
                for (int mf = 0; mf < 4; mf++)
#pragma unroll
                    for (int nf = 0; nf < 4; nf++)
                        mma_tf32(acc[mf][nf],
                                 af[mf][0], af[mf][1], af[mf][2], af[mf][3],
                                 bf[nf][2 * k2], bf[nf][2 * k2 + 1]);
            }
        }
        __syncthreads();
    }

#pragma unroll
    for (int nf = 0; nf < 4; nf++) {
        int c = n0 + wn0 + nf * 8 + 2 * q;
        float2 sc = *(const float2*)(scale + c);
        float2 sh = *(const float2*)(shift + c);
        float2 bi = make_float2(0.f, 0.f);
        if (bias) bi = *(const float2*)(bias + c);
#pragma unroll
        for (int mf = 0; mf < 4; mf++) {
            int r = m0 + wm0 + mf * 16 + g;
            float2 lo, hi;
            lo.x = (acc[mf][nf][0] + bi.x) * sc.x + sh.x;
            lo.y = (acc[mf][nf][1] + bi.y) * sc.y + sh.y;
            hi.x = (acc[mf][nf][2] + bi.x) * sc.x + sh.x;
            hi.y = (acc[mf][nf][3] + bi.y) * sc.y + sh.y;
            *(float2*)(C + (size_t)r * N + c) = lo;
            *(float2*)(C + (size_t)(r + 8) * N + c) = hi;
        }
    }
}

// ---------------------------------------------------------------------------
// round-to-tf32 prepass (RNA): out[i] = tf32(in[i])
// ---------------------------------------------------------------------------
__global__ void round_tf32(const float4* __restrict__ in, float4* __restrict__ out, int n4)
{
    int i = blockIdx.x * blockDim.x + threadIdx.x;
    if (i < n4) {
        uint4 r = cvt4(in[i]);
        out[i] = *(float4*)&r;
    }
}

// ---------------------------------------------------------------------------
// 32x32 tiled transpose with tf32 RNA rounding on store
// ---------------------------------------------------------------------------
__global__ void transpose32(const float* __restrict__ in, float* __restrict__ out,
                            int R, int C)
{
    __shared__ float t[32][33];
    const int c0 = blockIdx.x * 32, r0 = blockIdx.y * 32;
#pragma unroll
    for (int i = 0; i < 32; i += 8)
        t[threadIdx.y + i][threadIdx.x] = in[(size_t)(r0 + threadIdx.y + i) * C + c0 + threadIdx.x];
    __syncthreads();
#pragma unroll
    for (int i = 0; i < 32; i += 8)
        out[(size_t)(c0 + threadIdx.y + i) * R + r0 + threadIdx.x] =
            __uint_as_float(f2tf32(t[threadIdx.x][threadIdx.y + i]));
}

// ---------------------------------------------------------------------------
// tf32 flash attention: 256 threads (8 warps), 128 q-rows per block,
// persistent Q tile, K/V tiles of 64 rows. Dynamic smem 70656 B.
// grid (SEQ/128, BATCH*NHEADS).
// ---------------------------------------------------------------------------
#define QS_STRIDE 68
#define KS_STRIDE 68
#define VS_STRIDE 72
#define ATTN_SMEM ((128*QS_STRIDE + 64*KS_STRIDE + 64*VS_STRIDE) * 4)   // 70656

__global__ __launch_bounds__(256, 2)
void attn_tf32(const float* __restrict__ qkv, float* __restrict__ out)
{
    extern __shared__ uint32_t sm[];
    uint32_t* Qs = sm;                       // 128 x 68
    uint32_t* Ks = sm + 128 * QS_STRIDE;     // 64 x 68
    uint32_t* Vs = Ks + 64 * KS_STRIDE;      // 64 x 72

    const int tid  = threadIdx.x;
    const int lane = tid & 31;
    const int warp = tid >> 5;     // 0..7
    const int g = lane >> 2;
    const int q = lane & 3;
    const int s0 = blockIdx.x * 128;
    const int bh = blockIdx.y;
    const int b = bh / NHEADS;
    const int h = bh - b * NHEADS;

    const uint32_t qsb = smem_u32(Qs);
    const uint32_t ksb = smem_u32(Ks);
    const float* qbase = qkv + (size_t)b * SEQ * QKV_N + h * HDIM;
    const float* kbase = qbase + HID;
    const float* vbase = qbase + 2 * HID;

    // stage Q tile (128 rows) once
#pragma unroll
    for (int it = 0; it < 8; it++) {
        int u = tid + it * 256;
        int r = u >> 4, c4 = u & 15;
        float4 v = *(const float4*)(qbase + (size_t)(s0 + r) * QKV_N + c4 * 4);
        *(uint4*)(&Qs[r * QS_STRIDE + c4 * 4]) = cvt4(v);
    }

    float o_acc[8][4];
#pragma unroll
    for (int nf = 0; nf < 8; nf++)
#pragma unroll
        for (int cc = 0; cc < 4; cc++) o_acc[nf][cc] = 0.f;
    float m0r = -1e30f, m1r = -1e30f, l0r = 0.f, l1r = 0.f;
    const float sm_scale = 0.125f;

    const int src0 = (lane & ~3) | (q >> 1);
    const int src2 = (lane & ~3) | ((q >> 1) + 2);
    const int sel = q & 1;
    const int qrow = warp * 16 + (lane & 15);
    const uint32_t qrow_base = qsb + qrow * (QS_STRIDE * 4);
    const int qsel = lane >> 4;
    const int kfrow_l = lane & 7;
    const int kfsel = lane >> 3;

    for (int t = 0; t < SEQ / 64; t++) {
        const int j0 = t * 64;
        __syncthreads();   // prev tile's K/V reads done (also covers Q staging on t=0)
#pragma unroll
        for (int it = 0; it < 4; it++) {
            int u = tid + it * 256;
            int r = u >> 4, c4 = u & 15;
            float4 kv = *(const float4*)(kbase + (size_t)(j0 + r) * QKV_N + c4 * 4);
            *(uint4*)(&Ks[r * KS_STRIDE + c4 * 4]) = cvt4(kv);
            float4 vv = *(const float4*)(vbase + (size_t)(j0 + r) * QKV_N + c4 * 4);
            *(uint4*)(&Vs[r * VS_STRIDE + c4 * 4]) = cvt4(vv);
        }
        __syncthreads();

        // S = Q K^T, Q frags reloaded per ksp (register relief)
        float s[8][4];
#pragma unroll
        for (int nf = 0; nf < 8; nf++)
#pragma unroll
            for (int cc = 0; cc < 4; cc++) s[nf][cc] = 0.f;

#pragma unroll
        for (int ksp = 0; ksp < 4; ksp++) {
            uint32_t qa0[4], qa1[4];
            LDSM_X4(qa0[0], qa0[1], qa0[2], qa0[3],
                    qrow_base + (4 * ksp + qsel) * 16);
            LDSM_X4(qa1[0], qa1[1], qa1[2], qa1[3],
                    qrow_base + (4 * ksp + 2 + qsel) * 16);
#pragma unroll
            for (int nh = 0; nh < 2; nh++) {
                uint32_t kb[4][4];
#pragma unroll
                for (int nn = 0; nn < 4; nn++) {
                    int row = (nh * 4 + nn) * 8 + kfrow_l;
                    uint32_t addr = ksb + row * (KS_STRIDE * 4) +
                                    (4 * ksp + kfsel) * 16;
                    LDSM_X4(kb[nn][0], kb[nn][1], kb[nn][2], kb[nn][3], addr);
                }
#pragma unroll
                for (int nn = 0; nn < 4; nn++) {
                    mma_tf32(s[nh * 4 + nn], qa0[0], qa0[1], qa0[2], qa0[3],
                             kb[nn][0], kb[nn][1]);
                    mma_tf32(s[nh * 4 + nn], qa1[0], qa1[1], qa1[2], qa1[3],
                             kb[nn][2], kb[nn][3]);
                }
            }
        }

        // online softmax
        float mx0 = -1e30f, mx1 = -1e30f;
#pragma unroll
        for (int nf = 0; nf < 8; nf++) {
#pragma unroll
            for (int cc = 0; cc < 4; cc++) s[nf][cc] *= sm_scale;
            mx0 = fmaxf(mx0, fmaxf(s[nf][0], s[nf][1]));
            mx1 = fmaxf(mx1, fmaxf(s[nf][2], s[nf][3]));
        }
        mx0 = fmaxf(mx0, __shfl_xor_sync(0xffffffffu, mx0, 1));
        mx0 = fmaxf(mx0, __shfl_xor_sync(0xffffffffu, mx0, 2));
        mx1 = fmaxf(mx1, __shfl_xor_sync(0xffffffffu, mx1, 1));
        mx1 = fmaxf(mx1, __shfl_xor_sync(0xffffffffu, mx1, 2));
        float nm0 = fmaxf(m0r, mx0);
        float nm1 = fmaxf(m1r, mx1);
        float sum0 = 0.f, sum1 = 0.f;
#pragma unroll
        for (int nf = 0; nf < 8; nf++) {
            s[nf][0] = __expf(s[nf][0] - nm0);
            s[nf][1] = __expf(s[nf][1] - nm0);
            s[nf][2] = __expf(s[nf][2] - nm1);
            s[nf][3] = __expf(s[nf][3] - nm1);
            sum0 += s[nf][0] + s[nf][1];
            sum1 += s[nf][2] + s[nf][3];
        }
        sum0 += __shfl_xor_sync(0xffffffffu, sum0, 1);
        sum0 += __shfl_xor_sync(0xffffffffu, sum0, 2);
        sum1 += __shfl_xor_sync(0xffffffffu, sum1, 1);
        sum1 += __shfl_xor_sync(0xffffffffu, sum1, 2);
        float corr0 = __expf(m0r - nm0);
        float corr1 = __expf(m1r - nm1);
        l0r = l0r * corr0 + sum0;
        l1r = l1r * corr1 + sum1;
        m0r = nm0; m1r = nm1;
#pragma unroll
        for (int nf = 0; nf < 8; nf++) {
            o_acc[nf][0] *= corr0; o_acc[nf][1] *= corr0;
            o_acc[nf][2] *= corr1; o_acc[nf][3] *= corr1;
        }

        // P C-layout -> A-layout via shuffles; O += P @ V
#pragma unroll
        for (int ks = 0; ks < 8; ks++) {
            float v00 = __shfl_sync(0xffffffffu, s[ks][0], src0);
            float v01 = __shfl_sync(0xffffffffu, s[ks][1], src0);
            float v20 = __shfl_sync(0xffffffffu, s[ks][0], src2);
            float v21 = __shfl_sync(0xffffffffu, s[ks][1], src2);
            float v10 = __shfl_sync(0xffffffffu, s[ks][2], src0);
            float v11 = __shfl_sync(0xffffffffu, s[ks][3], src0);
            float v30 = __shfl_sync(0xffffffffu, s[ks][2], src2);
            float v31 = __shfl_sync(0xffffffffu, s[ks][3], src2);
            uint32_t pa0 = f2tf32(sel ? v01 : v00);
            uint32_t pa1 = f2tf32(sel ? v11 : v10);
            uint32_t pa2 = f2tf32(sel ? v21 : v20);
            uint32_t pa3 = f2tf32(sel ? v31 : v30);
#pragma unroll
            for (int nf = 0; nf < 8; nf++) {
                uint32_t b0 = Vs[(ks * 8 + q) * VS_STRIDE + nf * 8 + g];
                uint32_t b1 = Vs[(ks * 8 + q + 4) * VS_STRIDE + nf * 8 + g];
                mma_tf32(o_acc[nf], pa0, pa1, pa2, pa3, b0, b1);
            }
        }
    }

    // normalize, round to tf32 (feeds out-proj A-side), write
    float inv0 = 1.0f / l0r;
    float inv1 = 1.0f / l1r;
    int r0 = b * SEQ + s0 + warp * 16 + g;
#pragma unroll
    for (int nf = 0; nf < 8; nf++) {
        int c = h * HDIM + nf * 8 + 2 * q;
        float2 lo, hi;
        lo.x = __uint_as_float(f2tf32(o_acc[nf][0] * inv0));
        lo.y = __uint_as_float(f2tf32(o_acc[nf][1] * inv0));
        hi.x = __uint_as_float(f2tf32(o_acc[nf][2] * inv1));
        hi.y = __uint_as_float(f2tf32(o_acc[nf][3] * inv1));
        *(float2*)(out + (size_t)r0 * HID + c) = lo;
        *(float2*)(out + (size_t)(r0 + 8) * HID + c) = hi;
    }
}

// ---------------------------------------------------------------------------
extern "C" void kernel_launch(void* const* d_in, const int* in_sizes, int n_in,
                              void* d_out, int out_size)
{
    (void)in_sizes; (void)n_in; (void)out_size;
    const float* x      = (const float*)d_in[0];
    const float* Wqkv   = (const float*)d_in[1];
    const float* scale1 = (const float*)d_in[2];
    const float* shift1 = (const float*)d_in[3];
    const float* Wout   = (const float*)d_in[4];
    const float* bout   = (const float*)d_in[5];
    const float* scale2 = (const float*)d_in[6];
    const float* shift2 = (const float*)d_in[7];
    float* out = (float*)d_out;

    float *x_r = nullptr, *qkv_buf = nullptr, *o_buf = nullptr, *wt_qkv = nullptr, *wt_out = nullptr;
    cudaGetSymbolAddress((void**)&x_r, g_x);
    cudaGetSymbolAddress((void**)&qkv_buf, g_qkv);
    cudaGetSymbolAddress((void**)&o_buf, g_o);
    cudaGetSymbolAddress((void**)&wt_qkv, g_wt_qkv);
    cudaGetSymbolAddress((void**)&wt_out, g_wt_out);

    static bool attr_set = false;
    if (!attr_set) {
        cudaFuncSetAttribute(gemm_mma, cudaFuncAttributeMaxDynamicSharedMemorySize, GEMM_SMEM);
        cudaFuncSetAttribute(attn_tf32, cudaFuncAttributeMaxDynamicSharedMemorySize, ATTN_SMEM);
        attr_set = true;
    }

    // 0) pre-round x; transpose + round weights
    {
        int n4 = MTOT * HID / 4;
        round_tf32<<<(n4 + 255) / 256, 256>>>((const float4*)x, (float4*)x_r, n4);
        dim3 blk(32, 8);
        transpose32<<<dim3(QKV_N / 32, HID / 32), blk>>>(Wqkv, wt_qkv, HID, QKV_N);
        transpose32<<<dim3(HID / 32, HID / 32), blk>>>(Wout, wt_out, HID, HID);
    }
    // 1) QKV projection + SSF affine
    gemm_mma<<<dim3(QKV_N / 128, MTOT / 128), 256, GEMM_SMEM>>>(
        x_r, wt_qkv, qkv_buf, QKV_N, nullptr, scale1, shift1);
    // 2) attention (writes tf32-rounded o)
    attn_tf32<<<dim3(SEQ / 128, BATCH * NHEADS), 256, ATTN_SMEM>>>(qkv_buf, o_buf);
    // 3) out projection + bias + SSF affine
    gemm_mma<<<dim3(HID / 128, MTOT / 128), 256, GEMM_SMEM>>>(
        o_buf, wt_out, out, HID, bout, scale2, shift2);
}

// round 6
// speedup vs baseline: 1.0267x; 1.0267x over previous
#include <cuda_runtime.h>
#include <cuda_bf16.h>
#include <math.h>
#include <stdint.h>

#define BATCH   8
#define SEQ     1024
#define HID     768
#define NHEADS  12
#define HDIM    64
#define QKV_N   (3*HID)          // 2304
#define MTOT    (BATCH*SEQ)      // 8192

__device__ float g_x[(size_t)MTOT * HID];        // tf32-rounded x
__device__ float g_qkv[(size_t)MTOT * QKV_N];    // [B*S, 2304] (tf32-rounded)
__device__ float g_vt[(size_t)BATCH * NHEADS * HDIM * SEQ];  // V^T [bh][d][s]
__device__ float g_o[(size_t)MTOT * HID];        // [B*S, 768] (tf32-rounded)
__device__ float g_wt_qkv[(size_t)QKV_N * HID];  // Wqkv^T (tf32-rounded)
__device__ float g_wt_out[(size_t)HID * HID];    // Wout^T (tf32-rounded)

// ---------------------------------------------------------------------------
// helpers
// ---------------------------------------------------------------------------
__device__ __forceinline__ uint32_t smem_u32(const void* p) {
    uint32_t a;
    asm("{ .reg .u64 t; cvta.to.shared.u64 t, %1; cvt.u32.u64 %0, t; }" : "=r"(a) : "l"(p));
    return a;
}
__device__ __forceinline__ uint32_t f2tf32(float f) {
    uint32_t r;
    asm("cvt.rna.tf32.f32 %0, %1;" : "=r"(r) : "f"(f));
    return r;
}
__device__ __forceinline__ uint4 cvt4(float4 v) {
    uint4 r;
    r.x = f2tf32(v.x); r.y = f2tf32(v.y); r.z = f2tf32(v.z); r.w = f2tf32(v.w);
    return r;
}
__device__ __forceinline__ void mma_tf32(float* c,
                                         uint32_t a0, uint32_t a1, uint32_t a2, uint32_t a3,
                                         uint32_t b0, uint32_t b1) {
    asm volatile(
        "mma.sync.aligned.m16n8k8.row.col.f32.tf32.tf32.f32 "
        "{%0,%1,%2,%3}, {%4,%5,%6,%7}, {%8,%9}, {%0,%1,%2,%3};"
        : "+f"(c[0]), "+f"(c[1]), "+f"(c[2]), "+f"(c[3])
        : "r"(a0), "r"(a1), "r"(a2), "r"(a3), "r"(b0), "r"(b1));
}
#define LDSM_X4(r0, r1, r2, r3, addr) \
    asm volatile("ldmatrix.sync.aligned.m8n8.x4.shared.b16 {%0,%1,%2,%3}, [%4];" \
        : "=r"(r0), "=r"(r1), "=r"(r2), "=r"(r3) : "r"(addr))
__device__ __forceinline__ void cp16(uint32_t dst, const void* src) {
    asm volatile("cp.async.cg.shared.global [%0], [%1], 16;" :: "r"(dst), "l"(src));
}
#define CP_COMMIT() asm volatile("cp.async.commit_group;" ::: "memory")
#define CP_WAIT1()  asm volatile("cp.async.wait_group 1;" ::: "memory")
#define CP_WAIT0()  asm volatile("cp.async.wait_group 0;" ::: "memory")

// ---------------------------------------------------------------------------
// tf32 GEMM (mma.sync + cp.async + ldmatrix). Operands pre-rounded in memory.
// round_out=1 -> epilogue outputs rounded to tf32 (for tensors feeding MMAs).
// ---------------------------------------------------------------------------
#define KT       32
#define NCH      (768/KT)
#define STG_FLT  8192
#define GEMM_SMEM (3 * STG_FLT * 4)   // 98304

__global__ __launch_bounds__(256, 2)
void gemm_mma(const float* __restrict__ A, const float* __restrict__ Bt,
              float* __restrict__ C, int N,
              const float* __restrict__ bias,
              const float* __restrict__ scale,
              const float* __restrict__ shift,
              int round_out)
{
    extern __shared__ float smem[];
    const uint32_t sb = smem_u32(smem);
    const int tid  = threadIdx.x;
    const int lane = tid & 31;
    const int warp = tid >> 5;
    const int g = lane >> 2;
    const int q = lane & 3;
    const int wm0 = (warp >> 2) * 64;
    const int wn0 = (warp & 3) * 32;
    const int m0 = blockIdx.y * 128;
    const int n0 = blockIdx.x * 128;

    float acc[4][4][4];
#pragma unroll
    for (int mf = 0; mf < 4; mf++)
#pragma unroll
        for (int nf = 0; nf < 4; nf++)
#pragma unroll
            for (int cc = 0; cc < 4; cc++) acc[mf][nf][cc] = 0.f;

    const int r_ld = tid >> 3;
    const int u_ld = tid & 7;
    const int rowA_l = lane & 15;
    const int rowB_l = lane & 7;
    const int selA = lane >> 4;
    const int selB = lane >> 3;

#define LOAD_STAGE(s, kc) do { \
    uint32_t ab = sb + (s) * (STG_FLT * 4); \
    uint32_t bb = ab + 16384; \
    _Pragma("unroll") \
    for (int i = 0; i < 4; i++) { \
        int r = r_ld + i * 32; \
        uint32_t off = ((uint32_t)(r * 8 + (u_ld ^ (r & 7)))) << 4; \
        cp16(ab + off, A  + (size_t)(m0 + r) * 768 + (kc) * KT + u_ld * 4); \
        cp16(bb + off, Bt + (size_t)(n0 + r) * 768 + (kc) * KT + u_ld * 4); \
    } \
} while (0)

    LOAD_STAGE(0, 0); CP_COMMIT();
    LOAD_STAGE(1, 1); CP_COMMIT();

    for (int kc = 0; kc < NCH; kc++) {
        if (kc >= NCH - 2) { CP_WAIT0(); } else { CP_WAIT1(); }
        __syncthreads();
        if (kc + 2 < NCH) {
            LOAD_STAGE((kc + 2) % 3, kc + 2);
            CP_COMMIT();
        }
        const uint32_t ab = sb + (kc % 3) * (STG_FLT * 4);
        const uint32_t bb = ab + 16384;

#pragma unroll
        for (int ksp = 0; ksp < 2; ksp++) {
            uint32_t bf[4][4];
#pragma unroll
            for (int nf = 0; nf < 4; nf++) {
                int row = wn0 + nf * 8 + rowB_l;
                uint32_t addr = bb + row * 128 +
                                (((4 * ksp + selB) ^ (row & 7)) << 4);
                LDSM_X4(bf[nf][0], bf[nf][1], bf[nf][2], bf[nf][3], addr);
            }
#pragma unroll
            for (int k2 = 0; k2 < 2; k2++) {
                int ks = ksp * 2 + k2;
                uint32_t af[4][4];
#pragma unroll
                for (int mf = 0; mf < 4; mf++) {
                    int row = wm0 + mf * 16 + rowA_l;
                    uint32_t addr = ab + row * 128 +
                                    (((2 * ks + selA) ^ (row & 7)) << 4);
                    LDSM_X4(af[mf][0], af[mf][1], af[mf][2], af[mf][3], addr);
                }
#pragma unroll
                for (int mf = 0; mf < 4; mf++)
#pragma unroll
                    for (int nf = 0; nf < 4; nf++)
                        mma_tf32(acc[mf][nf],
                                 af[mf][0], af[mf][1], af[mf][2], af[mf][3],
                                 bf[nf][2 * k2], bf[nf][2 * k2 + 1]);
            }
        }
        __syncthreads();
    }

#pragma unroll
    for (int nf = 0; nf < 4; nf++) {
        int c = n0 + wn0 + nf * 8 + 2 * q;
        float2 sc = *(const float2*)(scale + c);
        float2 sh = *(const float2*)(shift + c);
        float2 bi = make_float2(0.f, 0.f);
        if (bias) bi = *(const float2*)(bias + c);
#pragma unroll
        for (int mf = 0; mf < 4; mf++) {
            int r = m0 + wm0 + mf * 16 + g;
            float v[4];
            v[0] = (acc[mf][nf][0] + bi.x) * sc.x + sh.x;
            v[1] = (acc[mf][nf][1] + bi.y) * sc.y + sh.y;
            v[2] = (acc[mf][nf][2] + bi.x) * sc.x + sh.x;
            v[3] = (acc[mf][nf][3] + bi.y) * sc.y + sh.y;
            if (round_out) {
#pragma unroll
                for (int i = 0; i < 4; i++) v[i] = __uint_as_float(f2tf32(v[i]));
            }
            *(float2*)(C + (size_t)r * N + c) = make_float2(v[0], v[1]);
            *(float2*)(C + (size_t)(r + 8) * N + c) = make_float2(v[2], v[3]);
        }
    }
}

// ---------------------------------------------------------------------------
// round-to-tf32 prepass (RNA)
// ---------------------------------------------------------------------------
__global__ void round_tf32(const float4* __restrict__ in, float4* __restrict__ out, int n4)
{
    int i = blockIdx.x * blockDim.x + threadIdx.x;
    if (i < n4) {
        uint4 r = cvt4(in[i]);
        out[i] = *(float4*)&r;
    }
}

// ---------------------------------------------------------------------------
// 32x32 tiled transpose with tf32 RNA rounding on store (weights)
// ---------------------------------------------------------------------------
__global__ void transpose32(const float* __restrict__ in, float* __restrict__ out,
                            int R, int C)
{
    __shared__ float t[32][33];
    const int c0 = blockIdx.x * 32, r0 = blockIdx.y * 32;
#pragma unroll
    for (int i = 0; i < 32; i += 8)
        t[threadIdx.y + i][threadIdx.x] = in[(size_t)(r0 + threadIdx.y + i) * C + c0 + threadIdx.x];
    __syncthreads();
#pragma unroll
    for (int i = 0; i < 32; i += 8)
        out[(size_t)(c0 + threadIdx.y + i) * R + r0 + threadIdx.x] =
            __uint_as_float(f2tf32(t[threadIdx.x][threadIdx.y + i]));
}

// ---------------------------------------------------------------------------
// V transpose: vt[bh][d][s] = qkv[(b*S+s)*2304 + 1536 + h*64 + d]
// grid (SEQ/32, HDIM/32, 96), block (32, 8). Values already rounded.
// ---------------------------------------------------------------------------
__global__ void vtrans(const float* __restrict__ qkv, float* __restrict__ vt)
{
    __shared__ float t[32][33];
    const int s0 = blockIdx.x * 32, d0 = blockIdx.y * 32;
    const int bh = blockIdx.z;
    const int b = bh / NHEADS, h = bh - b * NHEADS;
    const float* src = qkv + (size_t)b * SEQ * QKV_N + 2 * HID + h * HDIM;
#pragma unroll
    for (int i = 0; i < 32; i += 8)
        t[threadIdx.y + i][threadIdx.x] = src[(size_t)(s0 + threadIdx.y + i) * QKV_N + d0 + threadIdx.x];
    __syncthreads();
    float* dst = vt + (size_t)bh * HDIM * SEQ;
#pragma unroll
    for (int i = 0; i < 32; i += 8)
        dst[(size_t)(d0 + threadIdx.y + i) * SEQ + s0 + threadIdx.x] = t[threadIdx.x][threadIdx.y + i];
}

// ---------------------------------------------------------------------------
// tf32 flash attention: 256 threads (8 warps), 128 q-rows per block.
// All operands pre-rounded tf32 at rest -> cp.async + ldmatrix only.
// smem: Q 32KB swizzled + 2x K 16KB + 2x V(transposed) 16KB = 96KB.
// grid (SEQ/128, BATCH*NHEADS).
// ---------------------------------------------------------------------------
#define SWZ(r, u) (((((uint32_t)(r)) << 4) + (((uint32_t)(u)) ^ (((uint32_t)(r)) & 7))) << 4)
#define ATT_KB(s) (32768 + (s) * 16384)
#define ATT_VB(s) (65536 + (s) * 16384)
#define ATTN_SMEM 98304

__global__ __launch_bounds__(256, 2)
void attn_tf32(const float* __restrict__ qkv, const float* __restrict__ vt,
               float* __restrict__ out)
{
    extern __shared__ char sm[];
    const uint32_t sb = smem_u32(sm);

    const int tid  = threadIdx.x;
    const int lane = tid & 31;
    const int warp = tid >> 5;     // 0..7
    const int g = lane >> 2;
    const int q = lane & 3;
    const int s0 = blockIdx.x * 128;
    const int bh = blockIdx.y;
    const int b = bh / NHEADS;
    const int h = bh - b * NHEADS;

    const float* qbase = qkv + (size_t)b * SEQ * QKV_N + h * HDIM;
    const float* kbase = qbase + HID;
    const float* vtb   = vt + (size_t)bh * HDIM * SEQ;

    const int r_ld = tid >> 4;   // 0..15
    const int u_ld = tid & 15;   // 0..15

#define LOAD_KV(t_, s_) do { \
    int j0_ = (t_) * 64; \
    _Pragma("unroll") \
    for (int i = 0; i < 4; i++) { \
        int r = r_ld + i * 16; \
        cp16(sb + ATT_KB(s_) + SWZ(r, u_ld), kbase + (size_t)(j0_ + r) * QKV_N + u_ld * 4); \
        cp16(sb + ATT_VB(s_) + SWZ(r, u_ld), vtb + (size_t)r * SEQ + j0_ + u_ld * 4); \
    } \
} while (0)

    // prologue: Q tile + KV tile 0 in group 0
#pragma unroll
    for (int i = 0; i < 8; i++) {
        int r = r_ld + i * 16;
        cp16(sb + SWZ(r, u_ld), qbase + (size_t)(s0 + r) * QKV_N + u_ld * 4);
    }
    LOAD_KV(0, 0);
    CP_COMMIT();

    float o_acc[8][4];
#pragma unroll
    for (int nf = 0; nf < 8; nf++)
#pragma unroll
        for (int cc = 0; cc < 4; cc++) o_acc[nf][cc] = 0.f;
    float m0r = -1e30f, m1r = -1e30f, l0r = 0.f, l1r = 0.f;
    const float sm_scale = 0.125f;

    const int src0 = (lane & ~3) | (q >> 1);
    const int src2 = (lane & ~3) | ((q >> 1) + 2);
    const int sel = q & 1;
    const int qrow = warp * 16 + (lane & 15);
    const int qsel = lane >> 4;
    const int kfrow_l = lane & 7;
    const int kfsel = lane >> 3;

    for (int t = 0; t < SEQ / 64; t++) {
        if (t + 1 < SEQ / 64) {
            LOAD_KV(t + 1, (t + 1) & 1);
            CP_COMMIT();
            CP_WAIT1();
        } else {
            CP_WAIT0();
        }
        __syncthreads();
        const uint32_t kb_base = sb + ATT_KB(t & 1);
        const uint32_t vb_base = sb + ATT_VB(t & 1);

        // S = Q K^T
        float s[8][4];
#pragma unroll
        for (int nf = 0; nf < 8; nf++)
#pragma unroll
            for (int cc = 0; cc < 4; cc++) s[nf][cc] = 0.f;

#pragma unroll
        for (int ksp = 0; ksp < 4; ksp++) {
            uint32_t qa0[4], qa1[4];
            LDSM_X4(qa0[0], qa0[1], qa0[2], qa0[3],
                    sb + SWZ(qrow, 4 * ksp + qsel));
            LDSM_X4(qa1[0], qa1[1], qa1[2], qa1[3],
                    sb + SWZ(qrow, 4 * ksp + 2 + qsel));
#pragma unroll
            for (int nh = 0; nh < 2; nh++) {
                uint32_t kb[4][4];
#pragma unroll
                for (int nn = 0; nn < 4; nn++) {
                    int row = (nh * 4 + nn) * 8 + kfrow_l;
                    LDSM_X4(kb[nn][0], kb[nn][1], kb[nn][2], kb[nn][3],
                            kb_base + SWZ(row, 4 * ksp + kfsel));
                }
#pragma unroll
                for (int nn = 0; nn < 4; nn++) {
                    mma_tf32(s[nh * 4 + nn], qa0[0], qa0[1], qa0[2], qa0[3],
                             kb[nn][0], kb[nn][1]);
                    mma_tf32(s[nh * 4 + nn], qa1[0], qa1[1], qa1[2], qa1[3],
                             kb[nn][2], kb[nn][3]);
                }
            }
        }

        // online softmax
        float mx0 = -1e30f, mx1 = -1e30f;
#pragma unroll
        for (int nf = 0; nf < 8; nf++) {
#pragma unroll
            for (int cc = 0; cc < 4; cc++) s[nf][cc] *= sm_scale;
            mx0 = fmaxf(mx0, fmaxf(s[nf][0], s[nf][1]));
            mx1 = fmaxf(mx1, fmaxf(s[nf][2], s[nf][3]));
        }
        mx0 = fmaxf(mx0, __shfl_xor_sync(0xffffffffu, mx0, 1));
        mx0 = fmaxf(mx0, __shfl_xor_sync(0xffffffffu, mx0, 2));
        mx1 = fmaxf(mx1, __shfl_xor_sync(0xffffffffu, mx1, 1));
        mx1 = fmaxf(mx1, __shfl_xor_sync(0xffffffffu, mx1, 2));
        float nm0 = fmaxf(m0r, mx0);
        float nm1 = fmaxf(m1r, mx1);
        float sum0 = 0.f, sum1 = 0.f;
#pragma unroll
        for (int nf = 0; nf < 8; nf++) {
            s[nf][0] = __expf(s[nf][0] - nm0);
            s[nf][1] = __expf(s[nf][1] - nm0);
            s[nf][2] = __expf(s[nf][2] - nm1);
            s[nf][3] = __expf(s[nf][3] - nm1);
            sum0 += s[nf][0] + s[nf][1];
            sum1 += s[nf][2] + s[nf][3];
        }
        sum0 += __shfl_xor_sync(0xffffffffu, sum0, 1);
        sum0 += __shfl_xor_sync(0xffffffffu, sum0, 2);
        sum1 += __shfl_xor_sync(0xffffffffu, sum1, 1);
        sum1 += __shfl_xor_sync(0xffffffffu, sum1, 2);
        float corr0 = __expf(m0r - nm0);
        float corr1 = __expf(m1r - nm1);
        l0r = l0r * corr0 + sum0;
        l1r = l1r * corr1 + sum1;
        m0r = nm0; m1r = nm1;
#pragma unroll
        for (int nf = 0; nf < 8; nf++) {
            o_acc[nf][0] *= corr0; o_acc[nf][1] *= corr0;
            o_acc[nf][2] *= corr1; o_acc[nf][3] *= corr1;
        }

        // O += P @ V : V frags via ldmatrix from transposed tile
#pragma unroll
        for (int ksp = 0; ksp < 4; ksp++) {
            uint32_t vb[8][4];
#pragma unroll
            for (int nf = 0; nf < 8; nf++) {
                int row = nf * 8 + kfrow_l;
                LDSM_X4(vb[nf][0], vb[nf][1], vb[nf][2], vb[nf][3],
                        vb_base + SWZ(row, 4 * ksp + kfsel));
            }
#pragma unroll
            for (int k2 = 0; k2 < 2; k2++) {
                int ks = ksp * 2 + k2;
                float v00 = __shfl_sync(0xffffffffu, s[ks][0], src0);
                float v01 = __shfl_sync(0xffffffffu, s[ks][1], src0);
                float v20 = __shfl_sync(0xffffffffu, s[ks][0], src2);
                float v21 = __shfl_sync(0xffffffffu, s[ks][1], src2);
                float v10 = __shfl_sync(0xffffffffu, s[ks][2], src0);
                float v11 = __shfl_sync(0xffffffffu, s[ks][3], src0);
                float v30 = __shfl_sync(0xffffffffu, s[ks][2], src2);
                float v31 = __shfl_sync(0xffffffffu, s[ks][3], src2);
                uint32_t pa0 = f2tf32(sel ? v01 : v00);
                uint32_t pa1 = f2tf32(sel ? v11 : v10);
                uint32_t pa2 = f2tf32(sel ? v21 : v20);
                uint32_t pa3 = f2tf32(sel ? v31 : v30);
#pragma unroll
                for (int nf = 0; nf < 8; nf++)
                    mma_tf32(o_acc[nf], pa0, pa1, pa2, pa3,
                             vb[nf][2 * k2], vb[nf][2 * k2 + 1]);
            }
        }
        __syncthreads();
    }

    // normalize, round to tf32 (feeds out-proj A-side), write
    float inv0 = 1.0f / l0r;
    float inv1 = 1.0f / l1r;
    int r0 = b * SEQ + s0 + warp * 16 + g;
#pragma unroll
    for (int nf = 0; nf < 8; nf++) {
        int c = h * HDIM + nf * 8 + 2 * q;
        float2 lo, hi;
        lo.x = __uint_as_float(f2tf32(o_acc[nf][0] * inv0));
        lo.y = __uint_as_float(f2tf32(o_acc[nf][1] * inv0));
        hi.x = __uint_as_float(f2tf32(o_acc[nf][2] * inv1));
        hi.y = __uint_as_float(f2tf32(o_acc[nf][3] * inv1));
        *(float2*)(out + (size_t)r0 * HID + c) = lo;
        *(float2*)(out + (size_t)(r0 + 8) * HID + c) = hi;
    }
}

// ---------------------------------------------------------------------------
extern "C" void kernel_launch(void* const* d_in, const int* in_sizes, int n_in,
                              void* d_out, int out_size)
{
    (void)in_sizes; (void)n_in; (void)out_size;
    const float* x      = (const float*)d_in[0];
    const float* Wqkv   = (const float*)d_in[1];
    const float* scale1 = (const float*)d_in[2];
    const float* shift1 = (const float*)d_in[3];
    const float* Wout   = (const float*)d_in[4];
    const float* bout   = (const float*)d_in[5];
    const float* scale2 = (const float*)d_in[6];
    const float* shift2 = (const float*)d_in[7];
    float* out = (float*)d_out;

    float *x_r, *qkv_buf, *vt_buf, *o_buf, *wt_qkv, *wt_out;
    cudaGetSymbolAddress((void**)&x_r, g_x);
    cudaGetSymbolAddress((void**)&qkv_buf, g_qkv);
    cudaGetSymbolAddress((void**)&vt_buf, g_vt);
    cudaGetSymbolAddress((void**)&o_buf, g_o);
    cudaGetSymbolAddress((void**)&wt_qkv, g_wt_qkv);
    cudaGetSymbolAddress((void**)&wt_out, g_wt_out);

    static bool attr_set = false;
    if (!attr_set) {
        cudaFuncSetAttribute(gemm_mma, cudaFuncAttributeMaxDynamicSharedMemorySize, GEMM_SMEM);
        cudaFuncSetAttribute(attn_tf32, cudaFuncAttributeMaxDynamicSharedMemorySize, ATTN_SMEM);
        attr_set = true;
    }

    // 0) pre-round x; transpose + round weights
    {
        int n4 = MTOT * HID / 4;
        round_tf32<<<(n4 + 255) / 256, 256>>>((const float4*)x, (float4*)x_r, n4);
        dim3 blk(32, 8);
        transpose32<<<dim3(QKV_N / 32, HID / 32), blk>>>(Wqkv, wt_qkv, HID, QKV_N);
        transpose32<<<dim3(HID / 32, HID / 32), blk>>>(Wout, wt_out, HID, HID);
    }
    // 1) QKV projection + SSF affine (outputs rounded to tf32)
    gemm_mma<<<dim3(QKV_N / 128, MTOT / 128), 256, GEMM_SMEM>>>(
        x_r, wt_qkv, qkv_buf, QKV_N, nullptr, scale1, shift1, 1);
    // 1b) V transpose for ldmatrix-friendly layout
    vtrans<<<dim3(SEQ / 32, HDIM / 32, BATCH * NHEADS), dim3(32, 8)>>>(qkv_buf, vt_buf);
    // 2) attention (writes tf32-rounded o)
    attn_tf32<<<dim3(SEQ / 128, BATCH * NHEADS), 256, ATTN_SMEM>>>(qkv_buf, vt_buf, o_buf);
    // 3) out projection + bias + SSF affine (exact fp32 epilogue)
    gemm_mma<<<dim3(HID / 128, MTOT / 128), 256, GEMM_SMEM>>>(
        o_buf, wt_out, out, HID, bout, scale2, shift2, 0);
}